// round 4
// baseline (speedup 1.0000x reference)
#include <cuda_runtime.h>
#include <cstddef>
#include <cstdint>

// ---------------------------------------------------------------------------
// Problem constants
// ---------------------------------------------------------------------------
#define BB 4
#define LL 2048
#define DD 1024
#define HH 16
#define DK 64
#define DV 64
#define DFF 4096
#define ROWS (BB * LL)          // 8192
#define Y_ELEMS ((size_t)ROWS * DD)

// ---------------------------------------------------------------------------
// Scratch (device globals: allocation-free rule)
// ---------------------------------------------------------------------------
__device__ float g_x[ROWS * DD];
__device__ float g_q[ROWS * DD];
__device__ float g_k[ROWS * DD];
__device__ float g_vt[ROWS * DD];          // V transposed: [H*DV, ROWS]
__device__ float g_o[ROWS * DD];
__device__ float g_y[ROWS * DD];
__device__ float g_z[ROWS * DD];
__device__ float g_h[ROWS * DFF];
// tf32-rounded weights
__device__ float g_wq[DD * DD];
__device__ float g_wk[DD * DD];
__device__ float g_wv[DD * DD];
__device__ float g_fc[DD * DD];
__device__ float g_w1[DFF * DD];
__device__ float g_w2[DD * DFF];

// ---------------------------------------------------------------------------
// Helpers
// ---------------------------------------------------------------------------
__device__ __forceinline__ uint32_t smem_u32(const void* p) {
    uint32_t a;
    asm("{ .reg .u64 t; cvta.to.shared.u64 t, %1; cvt.u32.u64 %0, t; }" : "=r"(a) : "l"(p));
    return a;
}
__device__ __forceinline__ float tf32r(float x) {
    unsigned u = __float_as_uint(x), o;
    asm("cvt.rna.tf32.f32 %0, %1;" : "=r"(o) : "r"(u));
    return __uint_as_float(o);
}
__device__ __forceinline__ void cp16(uint32_t s, const void* g) {
    asm volatile("cp.async.cg.shared.global [%0], [%1], 16;" :: "r"(s), "l"(g));
}
#define CP_COMMIT() asm volatile("cp.async.commit_group;" ::: "memory")

__device__ __forceinline__ void mma8(float* c, const uint32_t* a, const uint32_t* b) {
    asm volatile(
        "mma.sync.aligned.m16n8k8.row.col.f32.tf32.tf32.f32 "
        "{%0,%1,%2,%3}, {%4,%5,%6,%7}, {%8,%9}, {%0,%1,%2,%3};"
        : "+f"(c[0]), "+f"(c[1]), "+f"(c[2]), "+f"(c[3])
        : "r"(a[0]), "r"(a[1]), "r"(a[2]), "r"(a[3]), "r"(b[0]), "r"(b[1]));
}

#define BKP 36

// ---------------------------------------------------------------------------
// BIG tf32 NT GEMM: C[M,N] = A[M,K] @ B[N,K]^T.  BM=256, BN=128, BK=32.
// 256 threads, warp tile 64x64, 4-stage cp.async pipeline, 1 CTA/SM.
// flags: 1=relu, 2=tf32-round output.
// ---------------------------------------------------------------------------
#define BSTG 4
#define BIG_STAGEF ((256 + 128) * BKP)

__global__ void __launch_bounds__(256, 1)
big_gemm(const float* __restrict__ A, const float* __restrict__ B,
         float* __restrict__ C,
         const float* __restrict__ bias, const float* __restrict__ resid, int flags,
         int K, int lda, int ldb, int ldc,
         long long sAo, long long sAi, long long sBo, long long sBi,
         long long sCo, long long sCi, int zInner) {
    extern __shared__ float sm[];
    uint32_t sbase = smem_u32(sm);

    int tid = threadIdx.x;
    int wid = tid >> 5, lane = tid & 31;
    int t4 = lane >> 2, tq = lane & 3;
    int wm = wid & 3, wn = wid >> 2;      // 4 x 2 warp grid, 64x64 tiles

    int z = blockIdx.z;
    int zo = z / zInner, zi = z - zo * zInner;
    A += (size_t)zo * sAo + (size_t)zi * sAi;
    B += (size_t)zo * sBo + (size_t)zi * sBi;
    size_t coff = (size_t)zo * sCo + (size_t)zi * sCi;
    C += coff;
    const float* Rp = resid ? resid + coff : nullptr;
    int bm = blockIdx.y * 256;
    int bn = blockIdx.x * 128;

    float acc[4][8][4];
#pragma unroll
    for (int mi = 0; mi < 4; mi++)
#pragma unroll
        for (int ni = 0; ni < 8; ni++)
#pragma unroll
            for (int j = 0; j < 4; j++) acc[mi][ni][j] = 0.f;

    int nk = K >> 5;

    auto load_stage = [&](int c) {
        int s = c & (BSTG - 1);
        int k0 = c << 5;
        uint32_t ab = sbase + (uint32_t)(s * BIG_STAGEF) * 4u;
        uint32_t bb = ab + 256u * BKP * 4u;
#pragma unroll
        for (int it = 0; it < 8; it++) {
            int f = it * 256 + tid;
            int row = f >> 3, c4 = (f & 7) << 2;
            cp16(ab + (uint32_t)(row * BKP + c4) * 4u,
                 A + (size_t)(bm + row) * lda + k0 + c4);
        }
#pragma unroll
        for (int it = 0; it < 4; it++) {
            int f = it * 256 + tid;
            int row = f >> 3, c4 = (f & 7) << 2;
            cp16(bb + (uint32_t)(row * BKP + c4) * 4u,
                 B + (size_t)(bn + row) * ldb + k0 + c4);
        }
        CP_COMMIT();
    };

    int npre = nk < 3 ? nk : 3;
    for (int c0 = 0; c0 < npre; c0++) load_stage(c0);

    for (int c = 0; c < nk; c++) {
        if (c + 3 < nk) {
            load_stage(c + 3);
            asm volatile("cp.async.wait_group 3;" ::: "memory");
        } else {
            asm volatile("cp.async.wait_group 0;" ::: "memory");
        }
        __syncthreads();
        const float* Asp = sm + (c & (BSTG - 1)) * BIG_STAGEF;
        const float* Bsp = Asp + 256 * BKP;
#pragma unroll
        for (int ks = 0; ks < 4; ks++) {
            int k0 = ks * 8;
            uint32_t a[4][4];
#pragma unroll
            for (int mi = 0; mi < 4; mi++) {
                int rb = wm * 64 + mi * 16 + t4;
                const float* p = Asp + rb * BKP + k0 + tq;
                a[mi][0] = __float_as_uint(p[0]);
                a[mi][1] = __float_as_uint(p[8 * BKP]);
                a[mi][2] = __float_as_uint(p[4]);
                a[mi][3] = __float_as_uint(p[8 * BKP + 4]);
            }
            uint32_t b[8][2];
#pragma unroll
            for (int ni = 0; ni < 8; ni++) {
                int cb = wn * 64 + ni * 8 + t4;
                const float* p = Bsp + cb * BKP + k0 + tq;
                b[ni][0] = __float_as_uint(p[0]);
                b[ni][1] = __float_as_uint(p[4]);
            }
#pragma unroll
            for (int mi = 0; mi < 4; mi++)
#pragma unroll
                for (int ni = 0; ni < 8; ni++)
                    mma8(acc[mi][ni], a[mi], b[ni]);
        }
        __syncthreads();
    }

    // ---- epilogue ----
#pragma unroll
    for (int mi = 0; mi < 4; mi++) {
#pragma unroll
        for (int half = 0; half < 2; half++) {
            int row = bm + wm * 64 + mi * 16 + t4 + half * 8;
#pragma unroll
            for (int ni = 0; ni < 8; ni++) {
                int col = bn + wn * 64 + ni * 8 + tq * 2;
                float v0 = acc[mi][ni][half * 2 + 0];
                float v1 = acc[mi][ni][half * 2 + 1];
                if (bias) { v0 += bias[col]; v1 += bias[col + 1]; }
                if (Rp) {
                    float2 r = *(const float2*)(Rp + (size_t)row * ldc + col);
                    v0 += r.x; v1 += r.y;
                }
                if (flags & 1) { v0 = fmaxf(v0, 0.f); v1 = fmaxf(v1, 0.f); }
                if (flags & 2) { v0 = tf32r(v0); v1 = tf32r(v1); }
                *(float2*)(C + (size_t)row * ldc + col) = make_float2(v0, v1);
            }
        }
    }
}

// ---------------------------------------------------------------------------
// Small NT GEMM (BN=64) for PV: BM=128, BK=32, 2-stage, 2 CTA/SM (proven).
// ---------------------------------------------------------------------------
template <int BN>
__global__ void __launch_bounds__(256, 2)
mma_gemm(const float* __restrict__ A, const float* __restrict__ B,
         float* __restrict__ C,
         const float* __restrict__ bias, const float* __restrict__ resid, int flags,
         int K, int lda, int ldb, int ldc,
         long long sAo, long long sAi, long long sBo, long long sBi,
         long long sCo, long long sCi, int zInner) {
    constexpr int WM = (BN == 128) ? 2 : 4;
    constexpr int WN = 8 / WM;
    constexpr int MT = 128 / (WM * 16);
    constexpr int NTL = BN / (WN * 8);
    constexpr int STAGEF = (128 + BN) * BKP;

    extern __shared__ float sm[];
    uint32_t sbase = smem_u32(sm);

    int tid = threadIdx.x;
    int wid = tid >> 5, lane = tid & 31;
    int t4 = lane >> 2, tq = lane & 3;
    int wm = wid % WM, wn = wid / WM;

    int z = blockIdx.z;
    int zo = z / zInner, zi = z - zo * zInner;
    A += (size_t)zo * sAo + (size_t)zi * sAi;
    B += (size_t)zo * sBo + (size_t)zi * sBi;
    size_t coff = (size_t)zo * sCo + (size_t)zi * sCi;
    C += coff;
    const float* Rp = resid ? resid + coff : nullptr;
    int bm = blockIdx.y * 128;
    int bn = blockIdx.x * BN;

    float acc[MT][NTL][4];
#pragma unroll
    for (int mi = 0; mi < MT; mi++)
#pragma unroll
        for (int ni = 0; ni < NTL; ni++)
#pragma unroll
            for (int j = 0; j < 4; j++) acc[mi][ni][j] = 0.f;

    int nk = K >> 5;

    auto load_stage = [&](int c, int s) {
        int k0 = c << 5;
        uint32_t ab = sbase + (uint32_t)(s * STAGEF) * 4u;
        uint32_t bb = ab + 128u * BKP * 4u;
#pragma unroll
        for (int it = 0; it < 4; it++) {
            int f = it * 256 + tid;
            int row = f >> 3, c4 = (f & 7) << 2;
            cp16(ab + (uint32_t)(row * BKP + c4) * 4u,
                 A + (size_t)(bm + row) * lda + k0 + c4);
        }
#pragma unroll
        for (int it = 0; it < BN / 32; it++) {
            int f = it * 256 + tid;
            int row = f >> 3, c4 = (f & 7) << 2;
            cp16(bb + (uint32_t)(row * BKP + c4) * 4u,
                 B + (size_t)(bn + row) * ldb + k0 + c4);
        }
        CP_COMMIT();
    };

    load_stage(0, 0);
    for (int c = 0; c < nk; c++) {
        int s = c & 1;
        if (c + 1 < nk) {
            load_stage(c + 1, (c + 1) & 1);
            asm volatile("cp.async.wait_group 1;" ::: "memory");
        } else {
            asm volatile("cp.async.wait_group 0;" ::: "memory");
        }
        __syncthreads();
        const float* Asp = sm + s * STAGEF;
        const float* Bsp = Asp + 128 * BKP;
#pragma unroll
        for (int ks = 0; ks < 4; ks++) {
            int k0 = ks * 8;
            uint32_t a[MT][4];
#pragma unroll
            for (int mi = 0; mi < MT; mi++) {
                int rb = wm * (MT * 16) + mi * 16 + t4;
                const float* p = Asp + rb * BKP + k0 + tq;
                a[mi][0] = __float_as_uint(p[0]);
                a[mi][1] = __float_as_uint(p[8 * BKP]);
                a[mi][2] = __float_as_uint(p[4]);
                a[mi][3] = __float_as_uint(p[8 * BKP + 4]);
            }
            uint32_t b[NTL][2];
#pragma unroll
            for (int ni = 0; ni < NTL; ni++) {
                int cb = wn * (NTL * 8) + ni * 8 + t4;
                const float* p = Bsp + cb * BKP + k0 + tq;
                b[ni][0] = __float_as_uint(p[0]);
                b[ni][1] = __float_as_uint(p[4]);
            }
#pragma unroll
            for (int mi = 0; mi < MT; mi++)
#pragma unroll
                for (int ni = 0; ni < NTL; ni++)
                    mma8(acc[mi][ni], a[mi], b[ni]);
        }
        __syncthreads();
    }

#pragma unroll
    for (int mi = 0; mi < MT; mi++) {
#pragma unroll
        for (int half = 0; half < 2; half++) {
            int row = bm + wm * (MT * 16) + mi * 16 + t4 + half * 8;
#pragma unroll
            for (int ni = 0; ni < NTL; ni++) {
                int col = bn + wn * (NTL * 8) + ni * 8 + tq * 2;
                float v0 = acc[mi][ni][half * 2 + 0];
                float v1 = acc[mi][ni][half * 2 + 1];
                if (bias) { v0 += bias[col]; v1 += bias[col + 1]; }
                if (Rp) {
                    float2 r = *(const float2*)(Rp + (size_t)row * ldc + col);
                    v0 += r.x; v1 += r.y;
                }
                if (flags & 1) { v0 = fmaxf(v0, 0.f); v1 = fmaxf(v1, 0.f); }
                if (flags & 2) { v0 = tf32r(v0); v1 = tf32r(v1); }
                *(float2*)(C + (size_t)row * ldc + col) = make_float2(v0, v1);
            }
        }
    }
}

// ---------------------------------------------------------------------------
// tf32 rounding copy (weights)
// ---------------------------------------------------------------------------
__global__ void cvt_kernel(const float* __restrict__ in, float* __restrict__ out, int n4) {
    int i = blockIdx.x * blockDim.x + threadIdx.x;
    if (i < n4) {
        float4 v = ((const float4*)in)[i];
        v.x = tf32r(v.x); v.y = tf32r(v.y); v.z = tf32r(v.z); v.w = tf32r(v.w);
        ((float4*)out)[i] = v;
    }
}

// ---------------------------------------------------------------------------
// LayerNorm (tf32-rounded output)
// ---------------------------------------------------------------------------
__global__ void ln_kernel(const float* __restrict__ in, float* __restrict__ out,
                          const float* __restrict__ gam, const float* __restrict__ bet) {
    int row = blockIdx.x;
    int tid = threadIdx.x;
    const float* x = in + (size_t)row * DD;
    float4 v = *(const float4*)(x + tid * 4);
    float s = v.x + v.y + v.z + v.w;
    float ss = v.x * v.x + v.y * v.y + v.z * v.z + v.w * v.w;
    __shared__ float red[16];
#pragma unroll
    for (int o = 16; o; o >>= 1) {
        s += __shfl_xor_sync(0xffffffffu, s, o);
        ss += __shfl_xor_sync(0xffffffffu, ss, o);
    }
    if ((tid & 31) == 0) { red[(tid >> 5) * 2] = s; red[(tid >> 5) * 2 + 1] = ss; }
    __syncthreads();
    float mu = 0.f, m2 = 0.f;
#pragma unroll
    for (int w = 0; w < 8; w++) { mu += red[2 * w]; m2 += red[2 * w + 1]; }
    mu *= (1.0f / DD);
    float var = m2 * (1.0f / DD) - mu * mu;
    float rstd = rsqrtf(var + 1e-6f);
    float4 gg = *(const float4*)(gam + tid * 4);
    float4 bb = *(const float4*)(bet + tid * 4);
    float4 o4;
    o4.x = tf32r((v.x - mu) * rstd * gg.x + bb.x);
    o4.y = tf32r((v.y - mu) * rstd * gg.y + bb.y);
    o4.z = tf32r((v.z - mu) * rstd * gg.z + bb.z);
    o4.w = tf32r((v.w - mu) * rstd * gg.w + bb.w);
    *(float4*)(out + (size_t)row * DD + tid * 4) = o4;
}

// ---------------------------------------------------------------------------
// Fast software exp
// ---------------------------------------------------------------------------
__device__ __forceinline__ float fast_exp(float x) {
    x = fmaxf(x, -87.0f);
    float t = x * 1.4426950408889634f;
    float fi = floorf(t);
    float y = fmaf(fi, -0.6931471805599453f, x);
    int i = (int)fi;
    float p = 1.9841270e-4f;
    p = fmaf(p, y, 1.3888889e-3f);
    p = fmaf(p, y, 8.3333333e-3f);
    p = fmaf(p, y, 4.1666667e-2f);
    p = fmaf(p, y, 1.6666666e-1f);
    p = fmaf(p, y, 0.5f);
    p = fmaf(p, y, 1.0f);
    p = fmaf(p, y, 1.0f);
    return __int_as_float((i + 127) << 23) * p;
}

// ---------------------------------------------------------------------------
// In-place prior/mask/softmax, next-head prefetch (output tf32-rounded)
// ---------------------------------------------------------------------------
__device__ __forceinline__ float bred(float v, float* red, bool domax) {
#pragma unroll
    for (int o = 16; o; o >>= 1) {
        float t = __shfl_xor_sync(0xffffffffu, v, o);
        v = domax ? fmaxf(v, t) : v + t;
    }
    if ((threadIdx.x & 31) == 0) red[threadIdx.x >> 5] = v;
    __syncthreads();
    float r = red[0];
#pragma unroll
    for (int i = 1; i < 8; i++) r = domax ? fmaxf(r, red[i]) : r + red[i];
    __syncthreads();
    return r;
}

__global__ void softmax_kernel(float* __restrict__ attn,
                               const float* __restrict__ prior,
                               const int* __restrict__ mask) {
    int q = blockIdx.x;
    int b = blockIdx.y;
    int tid = threadIdx.x;
    __shared__ float red[8];

    const float* pr = prior + ((size_t)b * LL + q) * LL;
    float4 p0 = *(const float4*)(pr + tid * 4);
    float4 p1 = *(const float4*)(pr + 1024 + tid * 4);
    const int* mp = mask + b * LL;
    int4 m0 = *(const int4*)(mp + tid * 4);
    int4 m1 = *(const int4*)(mp + 1024 + tid * 4);

    float f[8];
    f[0] = 0.125f * p0.x; f[1] = 0.125f * p0.y; f[2] = 0.125f * p0.z; f[3] = 0.125f * p0.w;
    f[4] = 0.125f * p1.x; f[5] = 0.125f * p1.y; f[6] = 0.125f * p1.z; f[7] = 0.125f * p1.w;
    int mk[8] = {m0.x, m0.y, m0.z, m0.w, m1.x, m1.y, m1.z, m1.w};

    float* srow0 = attn + (((size_t)(b * HH) * LL + q) * LL);
    float4 s0 = *(const float4*)(srow0 + tid * 4);
    float4 s1 = *(const float4*)(srow0 + 1024 + tid * 4);

    for (int h = 0; h < HH; h++) {
        float* srow = attn + (((size_t)(b * HH + h) * LL + q) * LL);
        float4 n0 = s0, n1 = s1;
        if (h + 1 < HH) {
            const float* nx = srow + (size_t)LL * LL;
            n0 = *(const float4*)(nx + tid * 4);
            n1 = *(const float4*)(nx + 1024 + tid * 4);
        }
        float v[8];
        v[0] = mk[0] ? s0.x * f[0] : -1e9f;
        v[1] = mk[1] ? s0.y * f[1] : -1e9f;
        v[2] = mk[2] ? s0.z * f[2] : -1e9f;
        v[3] = mk[3] ? s0.w * f[3] : -1e9f;
        v[4] = mk[4] ? s1.x * f[4] : -1e9f;
        v[5] = mk[5] ? s1.y * f[5] : -1e9f;
        v[6] = mk[6] ? s1.z * f[6] : -1e9f;
        v[7] = mk[7] ? s1.w * f[7] : -1e9f;
        float mloc = v[0];
#pragma unroll
        for (int i = 1; i < 8; i++) mloc = fmaxf(mloc, v[i]);
        float M = bred(mloc, red, true);
        float e[8];
        float ssum = 0.f;
#pragma unroll
        for (int i = 0; i < 8; i++) { e[i] = fast_exp(v[i] - M); ssum += e[i]; }
        float S = bred(ssum, red, false);
        float inv = 1.0f / S;
        float4 o0 = make_float4(tf32r(e[0] * inv), tf32r(e[1] * inv),
                                tf32r(e[2] * inv), tf32r(e[3] * inv));
        float4 o1 = make_float4(tf32r(e[4] * inv), tf32r(e[5] * inv),
                                tf32r(e[6] * inv), tf32r(e[7] * inv));
        *(float4*)(srow + tid * 4) = o0;
        *(float4*)(srow + 1024 + tid * 4) = o1;
        s0 = n0; s1 = n1;
    }
}

// ---------------------------------------------------------------------------
// Launch
// ---------------------------------------------------------------------------
#define SMEM_BIG (BIG_STAGEF * 4 * BSTG)        // 221184
#define SMEM_64  ((128 + 64) * BKP * 4 * 2)     // 55296

extern "C" void kernel_launch(void* const* d_in, const int* in_sizes, int n_in,
                              void* d_out, int out_size) {
    const float* src    = (const float*)d_in[0];
    const int*   mask   = (const int*)d_in[1];
    const float* prior  = (const float*)d_in[2];
    const float* ln1_g  = (const float*)d_in[3];
    const float* ln1_b  = (const float*)d_in[4];
    const float* wq     = (const float*)d_in[5];
    const float* wk     = (const float*)d_in[6];
    const float* wv     = (const float*)d_in[7];
    const float* fc_w   = (const float*)d_in[8];
    const float* ln2_g  = (const float*)d_in[9];
    const float* ln2_b  = (const float*)d_in[10];
    const float* w1_w   = (const float*)d_in[11];
    const float* w1_b   = (const float*)d_in[12];
    const float* w2_w   = (const float*)d_in[13];
    const float* w2_b   = (const float*)d_in[14];

    float* yout = (float*)d_out;
    float* attn = yout + Y_ELEMS;

    float* xb;  cudaGetSymbolAddress((void**)&xb, g_x);
    float* qb;  cudaGetSymbolAddress((void**)&qb, g_q);
    float* kb;  cudaGetSymbolAddress((void**)&kb, g_k);
    float* vtb; cudaGetSymbolAddress((void**)&vtb, g_vt);
    float* ob;  cudaGetSymbolAddress((void**)&ob, g_o);
    float* yb;  cudaGetSymbolAddress((void**)&yb, g_y);
    float* zb;  cudaGetSymbolAddress((void**)&zb, g_z);
    float* hb;  cudaGetSymbolAddress((void**)&hb, g_h);
    float* wqc; cudaGetSymbolAddress((void**)&wqc, g_wq);
    float* wkc; cudaGetSymbolAddress((void**)&wkc, g_wk);
    float* wvc; cudaGetSymbolAddress((void**)&wvc, g_wv);
    float* fcc; cudaGetSymbolAddress((void**)&fcc, g_fc);
    float* w1c; cudaGetSymbolAddress((void**)&w1c, g_w1);
    float* w2c; cudaGetSymbolAddress((void**)&w2c, g_w2);

    cudaFuncSetAttribute(big_gemm, cudaFuncAttributeMaxDynamicSharedMemorySize, SMEM_BIG);
    cudaFuncSetAttribute(mma_gemm<64>, cudaFuncAttributeMaxDynamicSharedMemorySize, SMEM_64);

    // 0) round weights to tf32
    cvt_kernel<<<(DD * DD / 4 + 255) / 256, 256>>>(wq, wqc, DD * DD / 4);
    cvt_kernel<<<(DD * DD / 4 + 255) / 256, 256>>>(wk, wkc, DD * DD / 4);
    cvt_kernel<<<(DD * DD / 4 + 255) / 256, 256>>>(wv, wvc, DD * DD / 4);
    cvt_kernel<<<(DD * DD / 4 + 255) / 256, 256>>>(fc_w, fcc, DD * DD / 4);
    cvt_kernel<<<(DFF * DD / 4 + 255) / 256, 256>>>(w1_w, w1c, DFF * DD / 4);
    cvt_kernel<<<(DFF * DD / 4 + 255) / 256, 256>>>(w2_w, w2c, DFF * DD / 4);

    // 1) LN1 (tf32-rounded)
    ln_kernel<<<ROWS, 256>>>(src, xb, ln1_g, ln1_b);

    // 2) Q, K projections
    {
        dim3 g(DD / 128, ROWS / 256, 1);
        big_gemm<<<g, 256, SMEM_BIG>>>(xb, wqc, qb, nullptr, nullptr, 2,
            DD, DD, DD, DD, 0, 0, 0, 0, 0, 0, 1);
        big_gemm<<<g, 256, SMEM_BIG>>>(xb, wkc, kb, nullptr, nullptr, 2,
            DD, DD, DD, DD, 0, 0, 0, 0, 0, 0, 1);
    }
    // 2b) V transposed: Vt[H*DV, ROWS] = wv @ x^T
    {
        dim3 g(ROWS / 128, DD / 256, 1);
        big_gemm<<<g, 256, SMEM_BIG>>>(wvc, xb, vtb, nullptr, nullptr, 2,
            DD, DD, DD, ROWS, 0, 0, 0, 0, 0, 0, 1);
    }

    // 3) Scores S = q . k per (b,h)
    {
        dim3 g(LL / 128, LL / 256, BB * HH);
        big_gemm<<<g, 256, SMEM_BIG>>>(qb, kb, attn, nullptr, nullptr, 0,
            DK, DD, DD, LL,
            (long long)LL * DD, (long long)DK,
            (long long)LL * DD, (long long)DK,
            (long long)HH * LL * LL, (long long)LL * LL,
            HH);
    }

    // 4) prior * mask * softmax (in place, tf32-rounded)
    softmax_kernel<<<dim3(LL, BB), 256>>>(attn, prior, mask);

    // 5) O = P @ Vt^T per (b,h): M=2048, N=64, K=2048
    {
        dim3 g(1, LL / 128, BB * HH);
        mma_gemm<64><<<g, 256, SMEM_64>>>(attn, vtb, ob, nullptr, nullptr, 2,
            LL, LL, ROWS, DD,
            (long long)HH * LL * LL, (long long)LL * LL,
            (long long)LL, (long long)DV * ROWS,
            (long long)LL * DD, (long long)DV,
            HH);
    }

    // 6) y = O @ fc^T + src
    {
        dim3 g(DD / 128, ROWS / 256, 1);
        big_gemm<<<g, 256, SMEM_BIG>>>(ob, fcc, yb, nullptr, src, 0,
            DD, DD, DD, DD, 0, 0, 0, 0, 0, 0, 1);
    }

    // 7) LN2 (tf32-rounded)
    ln_kernel<<<ROWS, 256>>>(yb, zb, ln2_g, ln2_b);

    // 8) h = relu(z @ w1^T + b1), tf32-rounded
    {
        dim3 g(DFF / 128, ROWS / 256, 1);
        big_gemm<<<g, 256, SMEM_BIG>>>(zb, w1c, hb, w1_b, nullptr, 1 | 2,
            DD, DD, DD, DFF, 0, 0, 0, 0, 0, 0, 1);
    }

    // 9) y_out = h @ w2^T + b2 + y
    {
        dim3 g(DD / 128, ROWS / 256, 1);
        big_gemm<<<g, 256, SMEM_BIG>>>(hb, w2c, yout, w2_b, yb, 0,
            DFF, DFF, DFF, DD, 0, 0, 0, 0, 0, 0, 1);
    }
}

// round 5
// speedup vs baseline: 1.5937x; 1.5937x over previous
#include <cuda_runtime.h>
#include <cuda_fp16.h>
#include <cstddef>
#include <cstdint>

// ---------------------------------------------------------------------------
// Problem constants
// ---------------------------------------------------------------------------
#define BB 4
#define LL 2048
#define DD 1024
#define HH 16
#define DK 64
#define DV 64
#define DFF 4096
#define ROWS (BB * LL)          // 8192
#define Y_ELEMS ((size_t)ROWS * DD)

// ---------------------------------------------------------------------------
// Scratch (device globals: allocation-free rule)
// ---------------------------------------------------------------------------
__device__ __half g_x16[ROWS * DD];
__device__ __half g_q16[ROWS * DD];
__device__ __half g_k16[ROWS * DD];
__device__ __half g_vt16[ROWS * DD];       // V^T: [H*DV, ROWS]
__device__ __half g_o16[ROWS * DD];
__device__ __half g_z16[ROWS * DD];
__device__ __half g_h16[(size_t)ROWS * DFF];
__device__ float  g_y[ROWS * DD];
__device__ __half g_p16[(size_t)BB * HH * LL * LL];   // fp16 copy of softmax P
// fp16 weights
__device__ __half g_wq16[DD * DD];
__device__ __half g_wk16[DD * DD];
__device__ __half g_wv16[DD * DD];
__device__ __half g_fc16[DD * DD];
__device__ __half g_w116[DFF * DD];
__device__ __half g_w216[DD * DFF];

// ---------------------------------------------------------------------------
// Helpers
// ---------------------------------------------------------------------------
__device__ __forceinline__ uint32_t smem_u32(const void* p) {
    uint32_t a;
    asm("{ .reg .u64 t; cvta.to.shared.u64 t, %1; cvt.u32.u64 %0, t; }" : "=r"(a) : "l"(p));
    return a;
}
__device__ __forceinline__ void cp16(uint32_t s, const void* g) {
    asm volatile("cp.async.cg.shared.global [%0], [%1], 16;" :: "r"(s), "l"(g));
}
#define CP_COMMIT() asm volatile("cp.async.commit_group;" ::: "memory")
#define SWZ(off) ((off) ^ (((off) >> 3) & 0x70))

#define LDSM4(r, addr) \
    asm volatile("ldmatrix.sync.aligned.m8n8.x4.shared.b16 {%0,%1,%2,%3}, [%4];" \
                 : "=r"((r)[0]), "=r"((r)[1]), "=r"((r)[2]), "=r"((r)[3]) : "r"(addr))

__device__ __forceinline__ void mma16(float* c, const uint32_t* a, uint32_t b0, uint32_t b1) {
    asm volatile(
        "mma.sync.aligned.m16n8k16.row.col.f32.f16.f16.f32 "
        "{%0,%1,%2,%3}, {%4,%5,%6,%7}, {%8,%9}, {%0,%1,%2,%3};"
        : "+f"(c[0]), "+f"(c[1]), "+f"(c[2]), "+f"(c[3])
        : "r"(a[0]), "r"(a[1]), "r"(a[2]), "r"(a[3]), "r"(b0), "r"(b1));
}

// ---------------------------------------------------------------------------
// fp16 NT GEMM: C[M,N] = A[M,K] @ B[N,K]^T  (A,B fp16 K-major, fp32 accum)
// BM=128, BK=64 halves, 3-stage cp.async, 256 threads, ldmatrix fragments.
// flags: 1 = relu, 2 = fp16 output (else fp32). bias/resid fp32.
// ---------------------------------------------------------------------------
template <int BN, int WM>
__global__ void __launch_bounds__(256, 2)
h_gemm(const __half* __restrict__ A, const __half* __restrict__ B, void* Cv,
       const float* __restrict__ bias, const float* __restrict__ resid, int flags,
       int K, int lda, int ldb, int ldc,
       long long sAo, long long sAi, long long sBo, long long sBi,
       long long sCo, long long sCi, int zInner) {
    constexpr int WMT = 128 / WM;            // warp tile M
    constexpr int MT = WMT / 16;             // m16 frags
    constexpr int STAGEB = (128 + BN) * 128; // bytes per stage
    extern __shared__ char smc[];
    uint32_t sbase = smem_u32(smc);

    int tid = threadIdx.x;
    int wid = tid >> 5, lane = tid & 31;
    int t4 = lane >> 2, tq = lane & 3;
    int wm = wid % WM, wn = wid / WM;
    int l16 = lane & 15, lh = (lane >> 4) << 3;

    int z = blockIdx.z;
    int zo = z / zInner, zi = z - zo * zInner;
    A += (size_t)zo * sAo + (size_t)zi * sAi;
    B += (size_t)zo * sBo + (size_t)zi * sBi;
    size_t coff = (size_t)zo * sCo + (size_t)zi * sCi;
    float* C32 = (float*)Cv + coff;
    __half* C16 = (__half*)Cv + coff;
    const float* Rp = resid ? resid + coff : nullptr;
    int bm = blockIdx.y * 128;
    int bn = blockIdx.x * BN;

    float acc[MT][4][4];
#pragma unroll
    for (int mi = 0; mi < MT; mi++)
#pragma unroll
        for (int t = 0; t < 4; t++)
#pragma unroll
            for (int j = 0; j < 4; j++) acc[mi][t][j] = 0.f;

    int nk = K >> 6;

    auto load_stage = [&](int c) {
        int s = c % 3;
        int k0 = c << 6;
        uint32_t ab = sbase + s * STAGEB;
        uint32_t bb = ab + 128 * 128;
#pragma unroll
        for (int it = 0; it < 4; it++) {
            int f = it * 256 + tid;
            int row = f >> 3, c8 = f & 7;
            uint32_t off = row * 128 + c8 * 16;
            cp16(ab + SWZ(off), A + (size_t)(bm + row) * lda + k0 + c8 * 8);
        }
#pragma unroll
        for (int it = 0; it < BN / 32; it++) {
            int f = it * 256 + tid;
            int row = f >> 3, c8 = f & 7;
            uint32_t off = row * 128 + c8 * 16;
            cp16(bb + SWZ(off), B + (size_t)(bn + row) * ldb + k0 + c8 * 8);
        }
        CP_COMMIT();
    };

    load_stage(0);
    if (nk > 1) load_stage(1);
    for (int c = 0; c < nk; c++) {
        if (c + 2 < nk) {
            load_stage(c + 2);
            asm volatile("cp.async.wait_group 2;" ::: "memory");
        } else {
            asm volatile("cp.async.wait_group 0;" ::: "memory");
        }
        __syncthreads();
        uint32_t as0 = sbase + (c % 3) * STAGEB;
        uint32_t bs0 = as0 + 128 * 128;
#pragma unroll
        for (int ks = 0; ks < 4; ks++) {
            int k0h = ks * 16;
            uint32_t a[MT][4];
#pragma unroll
            for (int mi = 0; mi < MT; mi++) {
                uint32_t off = (uint32_t)(wm * WMT + mi * 16 + l16) * 128 + (k0h + lh) * 2;
                LDSM4(a[mi], as0 + SWZ(off));
            }
            uint32_t b[2][4];
#pragma unroll
            for (int nj = 0; nj < 2; nj++) {
                uint32_t off = (uint32_t)(wn * 32 + nj * 16 + l16) * 128 + (k0h + lh) * 2;
                LDSM4(b[nj], bs0 + SWZ(off));
            }
#pragma unroll
            for (int mi = 0; mi < MT; mi++)
#pragma unroll
                for (int t = 0; t < 4; t++)
                    mma16(acc[mi][t], a[mi], b[t >> 1][t & 1], b[t >> 1][(t & 1) + 2]);
        }
        __syncthreads();
    }

    // ---- epilogue ----
#pragma unroll
    for (int mi = 0; mi < MT; mi++) {
#pragma unroll
        for (int hf = 0; hf < 2; hf++) {
            int row = bm + wm * WMT + mi * 16 + t4 + hf * 8;
#pragma unroll
            for (int t = 0; t < 4; t++) {
                int col = bn + wn * 32 + (t >> 1) * 16 + (t & 1) * 8 + tq * 2;
                float v0 = acc[mi][t][hf * 2 + 0];
                float v1 = acc[mi][t][hf * 2 + 1];
                if (bias) { v0 += bias[col]; v1 += bias[col + 1]; }
                if (Rp) {
                    float2 r = *(const float2*)(Rp + (size_t)row * ldc + col);
                    v0 += r.x; v1 += r.y;
                }
                if (flags & 1) { v0 = fmaxf(v0, 0.f); v1 = fmaxf(v1, 0.f); }
                if (flags & 2) {
                    *(__half2*)(C16 + (size_t)row * ldc + col) = __floats2half2_rn(v0, v1);
                } else {
                    *(float2*)(C32 + (size_t)row * ldc + col) = make_float2(v0, v1);
                }
            }
        }
    }
}

// ---------------------------------------------------------------------------
// One-shot weight conversion fp32 -> fp16 (all 6 matrices, blockIdx.y selects)
// ---------------------------------------------------------------------------
__global__ void cvt_all(const float* s0, const float* s1, const float* s2,
                        const float* s3, const float* s4, const float* s5,
                        __half* d0, __half* d1, __half* d2,
                        __half* d3, __half* d4, __half* d5) {
    int m = blockIdx.y;
    const float* s; __half* d; int n;
    switch (m) {
        case 0: s = s0; d = d0; n = DD * DD; break;
        case 1: s = s1; d = d1; n = DD * DD; break;
        case 2: s = s2; d = d2; n = DD * DD; break;
        case 3: s = s3; d = d3; n = DD * DD; break;
        case 4: s = s4; d = d4; n = DFF * DD; break;
        default: s = s5; d = d5; n = DFF * DD; break;
    }
    int i8 = (blockIdx.x * 256 + threadIdx.x) * 8;
    if (i8 < n) {
        float4 u = *(const float4*)(s + i8);
        float4 v = *(const float4*)(s + i8 + 4);
        __half2 h0 = __floats2half2_rn(u.x, u.y);
        __half2 h1 = __floats2half2_rn(u.z, u.w);
        __half2 h2 = __floats2half2_rn(v.x, v.y);
        __half2 h3 = __floats2half2_rn(v.z, v.w);
        __half2* dp = (__half2*)(d + i8);
        dp[0] = h0; dp[1] = h1; dp[2] = h2; dp[3] = h3;
    }
}

// ---------------------------------------------------------------------------
// LayerNorm: fp32 in, fp16 out
// ---------------------------------------------------------------------------
__global__ void ln_kernel(const float* __restrict__ in, __half* __restrict__ out,
                          const float* __restrict__ gam, const float* __restrict__ bet) {
    int row = blockIdx.x;
    int tid = threadIdx.x;
    const float* x = in + (size_t)row * DD;
    float4 v = *(const float4*)(x + tid * 4);
    float s = v.x + v.y + v.z + v.w;
    float ss = v.x * v.x + v.y * v.y + v.z * v.z + v.w * v.w;
    __shared__ float red[16];
#pragma unroll
    for (int o = 16; o; o >>= 1) {
        s += __shfl_xor_sync(0xffffffffu, s, o);
        ss += __shfl_xor_sync(0xffffffffu, ss, o);
    }
    if ((tid & 31) == 0) { red[(tid >> 5) * 2] = s; red[(tid >> 5) * 2 + 1] = ss; }
    __syncthreads();
    float mu = 0.f, m2 = 0.f;
#pragma unroll
    for (int w = 0; w < 8; w++) { mu += red[2 * w]; m2 += red[2 * w + 1]; }
    mu *= (1.0f / DD);
    float var = m2 * (1.0f / DD) - mu * mu;
    float rstd = rsqrtf(var + 1e-6f);
    float4 gg = *(const float4*)(gam + tid * 4);
    float4 bb = *(const float4*)(bet + tid * 4);
    __half2* op = (__half2*)(out + (size_t)row * DD + tid * 4);
    op[0] = __floats2half2_rn((v.x - mu) * rstd * gg.x + bb.x,
                              (v.y - mu) * rstd * gg.y + bb.y);
    op[1] = __floats2half2_rn((v.z - mu) * rstd * gg.z + bb.z,
                              (v.w - mu) * rstd * gg.w + bb.w);
}

// ---------------------------------------------------------------------------
// Fast software exp
// ---------------------------------------------------------------------------
__device__ __forceinline__ float fast_exp(float x) {
    x = fmaxf(x, -87.0f);
    float t = x * 1.4426950408889634f;
    float fi = floorf(t);
    float y = fmaf(fi, -0.6931471805599453f, x);
    int i = (int)fi;
    float p = 1.9841270e-4f;
    p = fmaf(p, y, 1.3888889e-3f);
    p = fmaf(p, y, 8.3333333e-3f);
    p = fmaf(p, y, 4.1666667e-2f);
    p = fmaf(p, y, 1.6666666e-1f);
    p = fmaf(p, y, 0.5f);
    p = fmaf(p, y, 1.0f);
    p = fmaf(p, y, 1.0f);
    return __int_as_float((i + 127) << 23) * p;
}

// ---------------------------------------------------------------------------
// In-place prior/mask/softmax; writes fp32 attn (output) + fp16 P copy for PV
// ---------------------------------------------------------------------------
__device__ __forceinline__ float bred(float v, float* red, bool domax) {
#pragma unroll
    for (int o = 16; o; o >>= 1) {
        float t = __shfl_xor_sync(0xffffffffu, v, o);
        v = domax ? fmaxf(v, t) : v + t;
    }
    if ((threadIdx.x & 31) == 0) red[threadIdx.x >> 5] = v;
    __syncthreads();
    float r = red[0];
#pragma unroll
    for (int i = 1; i < 8; i++) r = domax ? fmaxf(r, red[i]) : r + red[i];
    __syncthreads();
    return r;
}

__global__ void softmax_kernel(float* __restrict__ attn, __half* __restrict__ p16,
                               const float* __restrict__ prior,
                               const int* __restrict__ mask) {
    int q = blockIdx.x;
    int b = blockIdx.y;
    int tid = threadIdx.x;
    __shared__ float red[8];

    const float* pr = prior + ((size_t)b * LL + q) * LL;
    float4 p0 = *(const float4*)(pr + tid * 4);
    float4 p1 = *(const float4*)(pr + 1024 + tid * 4);
    const int* mp = mask + b * LL;
    int4 m0 = *(const int4*)(mp + tid * 4);
    int4 m1 = *(const int4*)(mp + 1024 + tid * 4);

    float f[8];
    f[0] = 0.125f * p0.x; f[1] = 0.125f * p0.y; f[2] = 0.125f * p0.z; f[3] = 0.125f * p0.w;
    f[4] = 0.125f * p1.x; f[5] = 0.125f * p1.y; f[6] = 0.125f * p1.z; f[7] = 0.125f * p1.w;
    int mk[8] = {m0.x, m0.y, m0.z, m0.w, m1.x, m1.y, m1.z, m1.w};

    float* srow0 = attn + (((size_t)(b * HH) * LL + q) * LL);
    float4 s0 = *(const float4*)(srow0 + tid * 4);
    float4 s1 = *(const float4*)(srow0 + 1024 + tid * 4);

    for (int h = 0; h < HH; h++) {
        size_t plane = ((size_t)(b * HH + h) * LL + q) * LL;
        float* srow = attn + plane;
        float4 n0 = s0, n1 = s1;
        if (h + 1 < HH) {
            const float* nx = srow + (size_t)LL * LL;
            n0 = *(const float4*)(nx + tid * 4);
            n1 = *(const float4*)(nx + 1024 + tid * 4);
        }
        float v[8];
        v[0] = mk[0] ? s0.x * f[0] : -1e9f;
        v[1] = mk[1] ? s0.y * f[1] : -1e9f;
        v[2] = mk[2] ? s0.z * f[2] : -1e9f;
        v[3] = mk[3] ? s0.w * f[3] : -1e9f;
        v[4] = mk[4] ? s1.x * f[4] : -1e9f;
        v[5] = mk[5] ? s1.y * f[5] : -1e9f;
        v[6] = mk[6] ? s1.z * f[6] : -1e9f;
        v[7] = mk[7] ? s1.w * f[7] : -1e9f;
        float mloc = v[0];
#pragma unroll
        for (int i = 1; i < 8; i++) mloc = fmaxf(mloc, v[i]);
        float M = bred(mloc, red, true);
        float e[8];
        float ssum = 0.f;
#pragma unroll
        for (int i = 0; i < 8; i++) { e[i] = fast_exp(v[i] - M); ssum += e[i]; }
        float S = bred(ssum, red, false);
        float inv = 1.0f / S;
#pragma unroll
        for (int i = 0; i < 8; i++) e[i] *= inv;
        *(float4*)(srow + tid * 4) = make_float4(e[0], e[1], e[2], e[3]);
        *(float4*)(srow + 1024 + tid * 4) = make_float4(e[4], e[5], e[6], e[7]);
        __half2* hp0 = (__half2*)(p16 + plane + tid * 4);
        hp0[0] = __floats2half2_rn(e[0], e[1]);
        hp0[1] = __floats2half2_rn(e[2], e[3]);
        __half2* hp1 = (__half2*)(p16 + plane + 1024 + tid * 4);
        hp1[0] = __floats2half2_rn(e[4], e[5]);
        hp1[1] = __floats2half2_rn(e[6], e[7]);
        s0 = n0; s1 = n1;
    }
}

// ---------------------------------------------------------------------------
// Launch
// ---------------------------------------------------------------------------
#define SMEM_H128 ((128 + 128) * 128 * 3)   // 98304
#define SMEM_H64  ((128 + 64) * 128 * 3)    // 73728

extern "C" void kernel_launch(void* const* d_in, const int* in_sizes, int n_in,
                              void* d_out, int out_size) {
    const float* src    = (const float*)d_in[0];
    const int*   mask   = (const int*)d_in[1];
    const float* prior  = (const float*)d_in[2];
    const float* ln1_g  = (const float*)d_in[3];
    const float* ln1_b  = (const float*)d_in[4];
    const float* wq     = (const float*)d_in[5];
    const float* wk     = (const float*)d_in[6];
    const float* wv     = (const float*)d_in[7];
    const float* fc_w   = (const float*)d_in[8];
    const float* ln2_g  = (const float*)d_in[9];
    const float* ln2_b  = (const float*)d_in[10];
    const float* w1_w   = (const float*)d_in[11];
    const float* w1_b   = (const float*)d_in[12];
    const float* w2_w   = (const float*)d_in[13];
    const float* w2_b   = (const float*)d_in[14];

    float* yout = (float*)d_out;
    float* attn = yout + Y_ELEMS;

    __half *xb, *qb, *kb, *vtb, *ob, *zb, *hb, *pb;
    float* yb;
    __half *wq16, *wk16, *wv16, *fc16, *w116, *w216;
    cudaGetSymbolAddress((void**)&xb, g_x16);
    cudaGetSymbolAddress((void**)&qb, g_q16);
    cudaGetSymbolAddress((void**)&kb, g_k16);
    cudaGetSymbolAddress((void**)&vtb, g_vt16);
    cudaGetSymbolAddress((void**)&ob, g_o16);
    cudaGetSymbolAddress((void**)&zb, g_z16);
    cudaGetSymbolAddress((void**)&hb, g_h16);
    cudaGetSymbolAddress((void**)&pb, g_p16);
    cudaGetSymbolAddress((void**)&yb, g_y);
    cudaGetSymbolAddress((void**)&wq16, g_wq16);
    cudaGetSymbolAddress((void**)&wk16, g_wk16);
    cudaGetSymbolAddress((void**)&wv16, g_wv16);
    cudaGetSymbolAddress((void**)&fc16, g_fc16);
    cudaGetSymbolAddress((void**)&w116, g_w116);
    cudaGetSymbolAddress((void**)&w216, g_w216);

    cudaFuncSetAttribute((const void*)h_gemm<128, 2>,
                         cudaFuncAttributeMaxDynamicSharedMemorySize, SMEM_H128);
    cudaFuncSetAttribute((const void*)h_gemm<64, 4>,
                         cudaFuncAttributeMaxDynamicSharedMemorySize, SMEM_H64);

    // 1) weights -> fp16 (single launch)
    {
        dim3 g((DFF * DD / 8 + 255) / 256, 6);
        cvt_all<<<g, 256>>>(wq, wk, wv, fc_w, w1_w, w2_w,
                            wq16, wk16, wv16, fc16, w116, w216);
    }

    // 2) LN1 -> x fp16
    ln_kernel<<<ROWS, 256>>>(src, xb, ln1_g, ln1_b);

    // 3,4) Q, K projections -> fp16
    {
        dim3 g(DD / 128, ROWS / 128, 1);
        h_gemm<128, 2><<<g, 256, SMEM_H128>>>(xb, wq16, qb, nullptr, nullptr, 2,
            DD, DD, DD, DD, 0, 0, 0, 0, 0, 0, 1);
        h_gemm<128, 2><<<g, 256, SMEM_H128>>>(xb, wk16, kb, nullptr, nullptr, 2,
            DD, DD, DD, DD, 0, 0, 0, 0, 0, 0, 1);
    }
    // 5) Vt = wv @ x^T -> fp16  [DD, ROWS]
    {
        dim3 g(ROWS / 128, DD / 128, 1);
        h_gemm<128, 2><<<g, 256, SMEM_H128>>>(wv16, xb, vtb, nullptr, nullptr, 2,
            DD, DD, DD, ROWS, 0, 0, 0, 0, 0, 0, 1);
    }

    // 6) Scores S = q . k per (b,h) -> fp32 raw into attn region   (ncu -s 5 lands here)
    {
        dim3 g(LL / 128, LL / 128, BB * HH);
        h_gemm<128, 2><<<g, 256, SMEM_H128>>>(qb, kb, attn, nullptr, nullptr, 0,
            DK, DD, DD, LL,
            (long long)LL * DD, (long long)DK,
            (long long)LL * DD, (long long)DK,
            (long long)HH * LL * LL, (long long)LL * LL,
            HH);
    }

    // 7) prior * mask * softmax -> attn fp32 + P fp16
    softmax_kernel<<<dim3(LL, BB), 256>>>(attn, pb, prior, mask);

    // 8) O = P @ Vt^T per (b,h) -> fp16
    {
        dim3 g(1, LL / 128, BB * HH);
        h_gemm<64, 4><<<g, 256, SMEM_H64>>>(pb, vtb, ob, nullptr, nullptr, 2,
            LL, LL, ROWS, DD,
            (long long)HH * LL * LL, (long long)LL * LL,
            (long long)LL, (long long)DV * ROWS,
            (long long)LL * DD, (long long)DV,
            HH);
    }

    // 9) y = O @ fc^T + src -> fp32
    {
        dim3 g(DD / 128, ROWS / 128, 1);
        h_gemm<128, 2><<<g, 256, SMEM_H128>>>(ob, fc16, yb, nullptr, src, 0,
            DD, DD, DD, DD, 0, 0, 0, 0, 0, 0, 1);
    }

    // 10) LN2 -> z fp16
    ln_kernel<<<ROWS, 256>>>(yb, zb, ln2_g, ln2_b);

    // 11) h = relu(z @ w1^T + b1) -> fp16
    {
        dim3 g(DFF / 128, ROWS / 128, 1);
        h_gemm<128, 2><<<g, 256, SMEM_H128>>>(zb, w116, hb, w1_b, nullptr, 1 | 2,
            DD, DD, DD, DFF, 0, 0, 0, 0, 0, 0, 1);
    }

    // 12) y_out = h @ w2^T + b2 + y -> fp32 d_out
    {
        dim3 g(DD / 128, ROWS / 128, 1);
        h_gemm<128, 2><<<g, 256, SMEM_H128>>>(hb, w216, yout, w2_b, yb, 0,
            DFF, DFF, DFF, DD, 0, 0, 0, 0, 0, 0, 1);
    }
}

// round 9
// speedup vs baseline: 1.6340x; 1.0253x over previous
#include <cuda_runtime.h>
#include <cuda_fp16.h>
#include <cstddef>
#include <cstdint>

// ---------------------------------------------------------------------------
// Problem constants
// ---------------------------------------------------------------------------
#define BB 4
#define LL 2048
#define DD 1024
#define HH 16
#define DK 64
#define DV 64
#define DFF 4096
#define ROWS (BB * LL)          // 8192
#define Y_ELEMS ((size_t)ROWS * DD)

// ---------------------------------------------------------------------------
// Scratch (device globals: allocation-free rule)
// ---------------------------------------------------------------------------
__device__ __half g_x16[ROWS * DD];
__device__ __half g_q16[ROWS * DD];
__device__ __half g_k16[ROWS * DD];
__device__ __half g_vt16[ROWS * DD];       // V^T: [H*DV, ROWS]
__device__ __half g_o16[ROWS * DD];
__device__ __half g_z16[ROWS * DD];
__device__ __half g_h16[(size_t)ROWS * DFF];
__device__ float  g_y[ROWS * DD];
__device__ __half g_e16[(size_t)BB * HH * LL * LL];   // unnormalized exp scores
__device__ float  g_inv[(size_t)BB * HH * LL];        // per-row 1/sum
// fp16 weights
__device__ __half g_wq16[DD * DD];
__device__ __half g_wk16[DD * DD];
__device__ __half g_wv16[DD * DD];
__device__ __half g_fc16[DD * DD];
__device__ __half g_w116[DFF * DD];
__device__ __half g_w216[DD * DFF];

// ---------------------------------------------------------------------------
// Helpers
// ---------------------------------------------------------------------------
__device__ __forceinline__ uint32_t smem_u32(const void* p) {
    uint32_t a;
    asm("{ .reg .u64 t; cvta.to.shared.u64 t, %1; cvt.u32.u64 %0, t; }" : "=r"(a) : "l"(p));
    return a;
}
__device__ __forceinline__ void cp16(uint32_t s, const void* g) {
    asm volatile("cp.async.cg.shared.global [%0], [%1], 16;" :: "r"(s), "l"(g));
}
#define CP_COMMIT() asm volatile("cp.async.commit_group;" ::: "memory")
#define SWZ(off) ((off) ^ (((off) >> 3) & 0x70))

#define LDSM4(r, addr) \
    asm volatile("ldmatrix.sync.aligned.m8n8.x4.shared.b16 {%0,%1,%2,%3}, [%4];" \
                 : "=r"((r)[0]), "=r"((r)[1]), "=r"((r)[2]), "=r"((r)[3]) : "r"(addr))

__device__ __forceinline__ void mma16(float* c, const uint32_t* a, uint32_t b0, uint32_t b1) {
    asm volatile(
        "mma.sync.aligned.m16n8k16.row.col.f32.f16.f16.f32 "
        "{%0,%1,%2,%3}, {%4,%5,%6,%7}, {%8,%9}, {%0,%1,%2,%3};"
        : "+f"(c[0]), "+f"(c[1]), "+f"(c[2]), "+f"(c[3])
        : "r"(a[0]), "r"(a[1]), "r"(a[2]), "r"(a[3]), "r"(b0), "r"(b1));
}

__device__ __forceinline__ float fast_exp(float x) {
    x = fmaxf(x, -87.0f);
    float t = x * 1.4426950408889634f;
    float fi = floorf(t);
    float y = fmaf(fi, -0.6931471805599453f, x);
    int i = (int)fi;
    float p = 1.9841270e-4f;
    p = fmaf(p, y, 1.3888889e-3f);
    p = fmaf(p, y, 8.3333333e-3f);
    p = fmaf(p, y, 4.1666667e-2f);
    p = fmaf(p, y, 1.6666666e-1f);
    p = fmaf(p, y, 0.5f);
    p = fmaf(p, y, 1.0f);
    p = fmaf(p, y, 1.0f);
    return __int_as_float((i + 127) << 23) * p;
}

// ---------------------------------------------------------------------------
// fp16 NT GEMM: C[M,N] = A[M,K] @ B[N,K]^T  (fp32 accum)
// BM=128, BK=64 halves, 3-stage cp.async, 256 threads, ldmatrix fragments.
// flags: 1=relu, 2=fp16 out, 4=exp(prior*mask*scale) epilogue -> fp16 E,
//        8=per-row scale (rowscale[z*LL+row]).
// ---------------------------------------------------------------------------
template <int BN, int WM>
__global__ void __launch_bounds__(256, 2)
h_gemm(const __half* __restrict__ A, const __half* __restrict__ B, void* Cv,
       const float* __restrict__ bias, const float* __restrict__ resid,
       const float* __restrict__ prior, const int* __restrict__ maskp,
       const float* __restrict__ rowscale, int flags,
       int K, int lda, int ldb, int ldc,
       long long sAo, long long sAi, long long sBo, long long sBi,
       long long sCo, long long sCi, int zInner) {
    constexpr int WMT = 128 / WM;
    constexpr int MT = WMT / 16;
    constexpr int STAGEB = (128 + BN) * 128;
    extern __shared__ char smc[];
    uint32_t sbase = smem_u32(smc);

    int tid = threadIdx.x;
    int wid = tid >> 5, lane = tid & 31;
    int t4 = lane >> 2, tq = lane & 3;
    int wm = wid % WM, wn = wid / WM;
    int l16 = lane & 15, lh = (lane >> 4) << 3;

    int z = blockIdx.z;
    int zo = z / zInner, zi = z - zo * zInner;
    A += (size_t)zo * sAo + (size_t)zi * sAi;
    B += (size_t)zo * sBo + (size_t)zi * sBi;
    size_t coff = (size_t)zo * sCo + (size_t)zi * sCi;
    float* C32 = (float*)Cv + coff;
    __half* C16 = (__half*)Cv + coff;
    const float* Rp = resid ? resid + coff : nullptr;
    const float* priorp = (flags & 4) ? prior + (size_t)zo * LL * LL : nullptr;
    const int* maskb = (flags & 4) ? maskp + zo * LL : nullptr;
    const float* rsp = (flags & 8) ? rowscale + (size_t)z * LL : nullptr;
    int bm = blockIdx.y * 128;
    int bn = blockIdx.x * BN;

    float acc[MT][4][4];
#pragma unroll
    for (int mi = 0; mi < MT; mi++)
#pragma unroll
        for (int t = 0; t < 4; t++)
#pragma unroll
            for (int j = 0; j < 4; j++) acc[mi][t][j] = 0.f;

    int nk = K >> 6;

    auto load_stage = [&](int c) {
        int s = c % 3;
        int k0 = c << 6;
        uint32_t ab = sbase + s * STAGEB;
        uint32_t bb = ab + 128 * 128;
#pragma unroll
        for (int it = 0; it < 4; it++) {
            int f = it * 256 + tid;
            int row = f >> 3, c8 = f & 7;
            uint32_t off = row * 128 + c8 * 16;
            cp16(ab + SWZ(off), A + (size_t)(bm + row) * lda + k0 + c8 * 8);
        }
#pragma unroll
        for (int it = 0; it < BN / 32; it++) {
            int f = it * 256 + tid;
            int row = f >> 3, c8 = f & 7;
            uint32_t off = row * 128 + c8 * 16;
            cp16(bb + SWZ(off), B + (size_t)(bn + row) * ldb + k0 + c8 * 8);
        }
        CP_COMMIT();
    };

    load_stage(0);
    if (nk > 1) load_stage(1);
    for (int c = 0; c < nk; c++) {
        if (c + 2 < nk) {
            load_stage(c + 2);
            asm volatile("cp.async.wait_group 2;" ::: "memory");
        } else {
            asm volatile("cp.async.wait_group 0;" ::: "memory");
        }
        __syncthreads();
        uint32_t as0 = sbase + (c % 3) * STAGEB;
        uint32_t bs0 = as0 + 128 * 128;
#pragma unroll
        for (int ks = 0; ks < 4; ks++) {
            int k0h = ks * 16;
            uint32_t a[MT][4];
#pragma unroll
            for (int mi = 0; mi < MT; mi++) {
                uint32_t off = (uint32_t)(wm * WMT + mi * 16 + l16) * 128 + (k0h + lh) * 2;
                LDSM4(a[mi], as0 + SWZ(off));
            }
            uint32_t b[2][4];
#pragma unroll
            for (int nj = 0; nj < 2; nj++) {
                uint32_t off = (uint32_t)(wn * 32 + nj * 16 + l16) * 128 + (k0h + lh) * 2;
                LDSM4(b[nj], bs0 + SWZ(off));
            }
#pragma unroll
            for (int mi = 0; mi < MT; mi++)
#pragma unroll
                for (int t = 0; t < 4; t++)
                    mma16(acc[mi][t], a[mi], b[t >> 1][t & 1], b[t >> 1][(t & 1) + 2]);
        }
        __syncthreads();
    }

    // ---- epilogue ----
#pragma unroll
    for (int mi = 0; mi < MT; mi++) {
#pragma unroll
        for (int hf = 0; hf < 2; hf++) {
            int row = bm + wm * WMT + mi * 16 + t4 + hf * 8;
            float rs = rsp ? rsp[row] : 0.f;
#pragma unroll
            for (int t = 0; t < 4; t++) {
                int col = bn + wn * 32 + (t >> 1) * 16 + (t & 1) * 8 + tq * 2;
                float v0 = acc[mi][t][hf * 2 + 0];
                float v1 = acc[mi][t][hf * 2 + 1];
                if (flags & 4) {
                    // prior * mask * 1/8 then exp(v - 8) -> fp16 E
                    float2 pw = *(const float2*)(priorp + (size_t)row * LL + col);
                    int mk0 = maskb[col], mk1 = maskb[col + 1];
                    float s0 = mk0 ? v0 * (pw.x * 0.125f) : -1e9f;
                    float s1 = mk1 ? v1 * (pw.y * 0.125f) : -1e9f;
                    *(__half2*)(C16 + (size_t)row * ldc + col) =
                        __floats2half2_rn(fast_exp(s0 - 8.0f), fast_exp(s1 - 8.0f));
                    continue;
                }
                if (bias) { v0 += bias[col]; v1 += bias[col + 1]; }
                if (Rp) {
                    float2 r = *(const float2*)(Rp + (size_t)row * ldc + col);
                    v0 += r.x; v1 += r.y;
                }
                if (flags & 8) { v0 *= rs; v1 *= rs; }
                if (flags & 1) { v0 = fmaxf(v0, 0.f); v1 = fmaxf(v1, 0.f); }
                if (flags & 2) {
                    *(__half2*)(C16 + (size_t)row * ldc + col) = __floats2half2_rn(v0, v1);
                } else {
                    *(float2*)(C32 + (size_t)row * ldc + col) = make_float2(v0, v1);
                }
            }
        }
    }
}

// ---------------------------------------------------------------------------
// Row sum + normalize: read E fp16 row, write attn fp32 = E/sum, store 1/sum.
// grid (LL, BB*HH), 256 threads, 8 elems/thread.
// ---------------------------------------------------------------------------
__global__ void rowsum_norm(const __half* __restrict__ E, float* __restrict__ attn,
                            float* __restrict__ inv) {
    size_t plane = ((size_t)blockIdx.y * LL + blockIdx.x) * LL;
    int tid = threadIdx.x;
    __shared__ float red[8];

    uint4 raw = *(const uint4*)(E + plane + tid * 8);
    __half2* h2 = (__half2*)&raw;
    float2 f[4];
    float s = 0.f;
#pragma unroll
    for (int i = 0; i < 4; i++) {
        f[i] = __half22float2(h2[i]);
        s += f[i].x + f[i].y;
    }
#pragma unroll
    for (int o = 16; o; o >>= 1) s += __shfl_xor_sync(0xffffffffu, s, o);
    if ((tid & 31) == 0) red[tid >> 5] = s;
    __syncthreads();
    float S = red[0];
#pragma unroll
    for (int i = 1; i < 8; i++) S += red[i];
    float iv = 1.0f / S;
    if (tid == 0) inv[(size_t)blockIdx.y * LL + blockIdx.x] = iv;

    float* op = attn + plane + tid * 8;
    *(float4*)op = make_float4(f[0].x * iv, f[0].y * iv, f[1].x * iv, f[1].y * iv);
    *(float4*)(op + 4) = make_float4(f[2].x * iv, f[2].y * iv, f[3].x * iv, f[3].y * iv);
}

// ---------------------------------------------------------------------------
// One-shot weight conversion fp32 -> fp16
// ---------------------------------------------------------------------------
__global__ void cvt_all(const float* s0, const float* s1, const float* s2,
                        const float* s3, const float* s4, const float* s5,
                        __half* d0, __half* d1, __half* d2,
                        __half* d3, __half* d4, __half* d5) {
    int m = blockIdx.y;
    const float* s; __half* d; int n;
    switch (m) {
        case 0: s = s0; d = d0; n = DD * DD; break;
        case 1: s = s1; d = d1; n = DD * DD; break;
        case 2: s = s2; d = d2; n = DD * DD; break;
        case 3: s = s3; d = d3; n = DD * DD; break;
        case 4: s = s4; d = d4; n = DFF * DD; break;
        default: s = s5; d = d5; n = DFF * DD; break;
    }
    int i8 = (blockIdx.x * 256 + threadIdx.x) * 8;
    if (i8 < n) {
        float4 u = *(const float4*)(s + i8);
        float4 v = *(const float4*)(s + i8 + 4);
        __half2* dp = (__half2*)(d + i8);
        dp[0] = __floats2half2_rn(u.x, u.y);
        dp[1] = __floats2half2_rn(u.z, u.w);
        dp[2] = __floats2half2_rn(v.x, v.y);
        dp[3] = __floats2half2_rn(v.z, v.w);
    }
}

// ---------------------------------------------------------------------------
// LayerNorm: fp32 in, fp16 out
// ---------------------------------------------------------------------------
__global__ void ln_kernel(const float* __restrict__ in, __half* __restrict__ out,
                          const float* __restrict__ gam, const float* __restrict__ bet) {
    int row = blockIdx.x;
    int tid = threadIdx.x;
    const float* x = in + (size_t)row * DD;
    float4 v = *(const float4*)(x + tid * 4);
    float s = v.x + v.y + v.z + v.w;
    float ss = v.x * v.x + v.y * v.y + v.z * v.z + v.w * v.w;
    __shared__ float red[16];
#pragma unroll
    for (int o = 16; o; o >>= 1) {
        s += __shfl_xor_sync(0xffffffffu, s, o);
        ss += __shfl_xor_sync(0xffffffffu, ss, o);
    }
    if ((tid & 31) == 0) { red[(tid >> 5) * 2] = s; red[(tid >> 5) * 2 + 1] = ss; }
    __syncthreads();
    float mu = 0.f, m2 = 0.f;
#pragma unroll
    for (int w = 0; w < 8; w++) { mu += red[2 * w]; m2 += red[2 * w + 1]; }
    mu *= (1.0f / DD);
    float var = m2 * (1.0f / DD) - mu * mu;
    float rstd = rsqrtf(var + 1e-6f);
    float4 gg = *(const float4*)(gam + tid * 4);
    float4 bb = *(const float4*)(bet + tid * 4);
    __half2* op = (__half2*)(out + (size_t)row * DD + tid * 4);
    op[0] = __floats2half2_rn((v.x - mu) * rstd * gg.x + bb.x,
                              (v.y - mu) * rstd * gg.y + bb.y);
    op[1] = __floats2half2_rn((v.z - mu) * rstd * gg.z + bb.z,
                              (v.w - mu) * rstd * gg.w + bb.w);
}

// ---------------------------------------------------------------------------
// Launch
// ---------------------------------------------------------------------------
#define SMEM_H128 ((128 + 128) * 128 * 3)   // 98304
#define SMEM_H64  ((128 + 64) * 128 * 3)    // 73728

extern "C" void kernel_launch(void* const* d_in, const int* in_sizes, int n_in,
                              void* d_out, int out_size) {
    const float* src    = (const float*)d_in[0];
    const int*   mask   = (const int*)d_in[1];
    const float* prior  = (const float*)d_in[2];
    const float* ln1_g  = (const float*)d_in[3];
    const float* ln1_b  = (const float*)d_in[4];
    const float* wq     = (const float*)d_in[5];
    const float* wk     = (const float*)d_in[6];
    const float* wv     = (const float*)d_in[7];
    const float* fc_w   = (const float*)d_in[8];
    const float* ln2_g  = (const float*)d_in[9];
    const float* ln2_b  = (const float*)d_in[10];
    const float* w1_w   = (const float*)d_in[11];
    const float* w1_b   = (const float*)d_in[12];
    const float* w2_w   = (const float*)d_in[13];
    const float* w2_b   = (const float*)d_in[14];

    float* yout = (float*)d_out;
    float* attn = yout + Y_ELEMS;

    __half *xb, *qb, *kb, *vtb, *ob, *zb, *hb, *eb;
    float *yb, *invb;
    __half *wq16, *wk16, *wv16, *fc16, *w116, *w216;
    cudaGetSymbolAddress((void**)&xb, g_x16);
    cudaGetSymbolAddress((void**)&qb, g_q16);
    cudaGetSymbolAddress((void**)&kb, g_k16);
    cudaGetSymbolAddress((void**)&vtb, g_vt16);
    cudaGetSymbolAddress((void**)&ob, g_o16);
    cudaGetSymbolAddress((void**)&zb, g_z16);
    cudaGetSymbolAddress((void**)&hb, g_h16);
    cudaGetSymbolAddress((void**)&eb, g_e16);
    cudaGetSymbolAddress((void**)&yb, g_y);
    cudaGetSymbolAddress((void**)&invb, g_inv);
    cudaGetSymbolAddress((void**)&wq16, g_wq16);
    cudaGetSymbolAddress((void**)&wk16, g_wk16);
    cudaGetSymbolAddress((void**)&wv16, g_wv16);
    cudaGetSymbolAddress((void**)&fc16, g_fc16);
    cudaGetSymbolAddress((void**)&w116, g_w116);
    cudaGetSymbolAddress((void**)&w216, g_w216);

    cudaFuncSetAttribute((const void*)h_gemm<128, 2>,
                         cudaFuncAttributeMaxDynamicSharedMemorySize, SMEM_H128);
    cudaFuncSetAttribute((const void*)h_gemm<64, 4>,
                         cudaFuncAttributeMaxDynamicSharedMemorySize, SMEM_H64);

    // 1) weights -> fp16
    {
        dim3 g((DFF * DD / 8 + 255) / 256, 6);
        cvt_all<<<g, 256>>>(wq, wk, wv, fc_w, w1_w, w2_w,
                            wq16, wk16, wv16, fc16, w116, w216);
    }

    // 2) LN1 -> x fp16
    ln_kernel<<<ROWS, 256>>>(src, xb, ln1_g, ln1_b);

    // 3,4) Q, K projections -> fp16
    {
        dim3 g(DD / 128, ROWS / 128, 1);
        h_gemm<128, 2><<<g, 256, SMEM_H128>>>(xb, wq16, qb, nullptr, nullptr,
            nullptr, nullptr, nullptr, 2,
            DD, DD, DD, DD, 0, 0, 0, 0, 0, 0, 1);
        h_gemm<128, 2><<<g, 256, SMEM_H128>>>(xb, wk16, kb, nullptr, nullptr,
            nullptr, nullptr, nullptr, 2,
            DD, DD, DD, DD, 0, 0, 0, 0, 0, 0, 1);
    }
    // 5) Vt = wv @ x^T -> fp16  [DD, ROWS]
    {
        dim3 g(ROWS / 128, DD / 128, 1);
        h_gemm<128, 2><<<g, 256, SMEM_H128>>>(wv16, xb, vtb, nullptr, nullptr,
            nullptr, nullptr, nullptr, 2,
            DD, DD, DD, ROWS, 0, 0, 0, 0, 0, 0, 1);
    }

    // 6) E = exp(prior*mask*scale*(q.k) - 8) -> fp16, per (b,h)
    {
        dim3 g(LL / 128, LL / 128, BB * HH);
        h_gemm<128, 2><<<g, 256, SMEM_H128>>>(qb, kb, eb, nullptr, nullptr,
            prior, mask, nullptr, 4,
            DK, DD, DD, LL,
            (long long)LL * DD, (long long)DK,
            (long long)LL * DD, (long long)DK,
            (long long)HH * LL * LL, (long long)LL * LL,
            HH);
    }

    // 7) row sums -> attn fp32 (normalized) + inv
    rowsum_norm<<<dim3(LL, BB * HH), 256>>>(eb, attn, invb);

    // 8) O = (E @ Vt^T) * inv per (b,h) -> fp16
    {
        dim3 g(1, LL / 128, BB * HH);
        h_gemm<64, 4><<<g, 256, SMEM_H64>>>(eb, vtb, ob, nullptr, nullptr,
            nullptr, nullptr, invb, 2 | 8,
            LL, LL, ROWS, DD,
            (long long)HH * LL * LL, (long long)LL * LL,
            (long long)LL, (long long)DV * ROWS,
            (long long)LL * DD, (long long)DV,
            HH);
    }

    // 9) y = O @ fc^T + src -> fp32
    {
        dim3 g(DD / 128, ROWS / 128, 1);
        h_gemm<128, 2><<<g, 256, SMEM_H128>>>(ob, fc16, yb, nullptr, src,
            nullptr, nullptr, nullptr, 0,
            DD, DD, DD, DD, 0, 0, 0, 0, 0, 0, 1);
    }

    // 10) LN2 -> z fp16
    ln_kernel<<<ROWS, 256>>>(yb, zb, ln2_g, ln2_b);

    // 11) h = relu(z @ w1^T + b1) -> fp16
    {
        dim3 g(DFF / 128, ROWS / 128, 1);
        h_gemm<128, 2><<<g, 256, SMEM_H128>>>(zb, w116, hb, w1_b, nullptr,
            nullptr, nullptr, nullptr, 1 | 2,
            DD, DD, DD, DFF, 0, 0, 0, 0, 0, 0, 1);
    }

    // 12) y_out = h @ w2^T + b2 + y -> fp32 d_out
    {
        dim3 g(DD / 128, ROWS / 128, 1);
        h_gemm<128, 2><<<g, 256, SMEM_H128>>>(hb, w216, yout, w2_b, yb,
            nullptr, nullptr, nullptr, 0,
            DFF, DFF, DFF, DD, 0, 0, 0, 0, 0, 0, 1);
    }
}